// round 6
// baseline (speedup 1.0000x reference)
#include <cuda_runtime.h>
#include <cstdint>

// AdjustableModePooling:
//   x: (64, 65536, 10) f32 of integer labels 0..9, flat-viewed as (B=64, C=10, D=65536)
//   window K1=8 along D, mode per window (ties -> smallest value)
//   out flat index = c*(8192*64) + j*64 + b
//
// R6: cp.async double-buffered pipeline, 4 tiles per block.
//  - warp w copies row w and consumes row w -> no CTA barrier on the input path
//  - cp.async.cg bypasses L1 (kills the LDG burst contention in the L1tex queue)
//  - s_out double-buffered -> exactly one __syncthreads per tile (for the transpose)

static constexpr unsigned B  = 64;
static constexpr unsigned C  = 10;
static constexpr unsigned D  = 65536;
static constexpr unsigned NJ = 8192;     // (D-8)/8+1
static constexpr unsigned JT = 64;       // windows per tile (per row)
static constexpr unsigned RT = 8;        // rows per block = warps per block
static constexpr unsigned NT = 4;        // tiles per block

#define CP_ASYNC16(dst_u32, src_ptr) \
    asm volatile("cp.async.cg.shared.global [%0], [%1], 16;\n" :: "r"(dst_u32), "l"(src_ptr))
#define CP_COMMIT() asm volatile("cp.async.commit_group;\n")
#define CP_WAIT(n)  asm volatile("cp.async.wait_group %0;\n" :: "n"(n))

__device__ __forceinline__ unsigned kmax(unsigned a, unsigned b) { return a > b ? a : b; }

__device__ __forceinline__ unsigned long long hist4(float a, float b_, float c_, float d_)
{
    // fma(f,4,2^23): bits = 0x4B000000 | 4v (exact for v in 0..9); bits&63 == 4v
    unsigned long long h = 0ull;
    h += 1ull << (__float_as_uint(__fmaf_rn(a,  4.0f, 8388608.0f)) & 63u);
    h += 1ull << (__float_as_uint(__fmaf_rn(b_, 4.0f, 8388608.0f)) & 63u);
    h += 1ull << (__float_as_uint(__fmaf_rn(c_, 4.0f, 8388608.0f)) & 63u);
    h += 1ull << (__float_as_uint(__fmaf_rn(d_, 4.0f, 8388608.0f)) & 63u);
    return h;
}

__device__ __forceinline__ float window_mode(float4 v0, float4 v1)
{
    unsigned long long acc = hist4(v0.x, v0.y, v0.z, v0.w)
                           + hist4(v1.x, v1.y, v1.z, v1.w);
    unsigned lo = (unsigned)acc;          // counts of v=0..7 in nibbles
    unsigned hi = (unsigned)(acc >> 32);  // counts of v=8,9

    // key_v = (count_v << 4) | (15 - v); max key wins; tie -> smallest v.
    unsigned k0 = ((lo << 4)  & 0xF0u) | 15u;
    unsigned k1 = ( lo        & 0xF0u) | 14u;
    unsigned k2 = ((lo >> 4)  & 0xF0u) | 13u;
    unsigned k3 = ((lo >> 8)  & 0xF0u) | 12u;
    unsigned k4 = ((lo >> 12) & 0xF0u) | 11u;
    unsigned k5 = ((lo >> 16) & 0xF0u) | 10u;
    unsigned k6 = ((lo >> 20) & 0xF0u) |  9u;
    unsigned k7 = ((lo >> 24) & 0xF0u) |  8u;
    unsigned k8 = ((hi << 4)  & 0xF0u) |  7u;
    unsigned k9 = ( hi        & 0xF0u) |  6u;

    unsigned m = kmax(kmax(kmax(k0, k1), kmax(k2, k3)),
                      kmax(kmax(k4, k5), kmax(k6, k7)));
    m = kmax(m, kmax(k8, k9));

    // mode = 15 - (m & 15) = (~m) & 15 ; int->float via exponent magic
    unsigned r = (~m) & 15u;
    return __uint_as_float(0x4B000000u | r) - 8388608.0f;
}

__global__ __launch_bounds__(256, 6)
void mode_pool_kernel(const float* __restrict__ x, float* __restrict__ out)
{
    __shared__ float s_in[2][RT * JT * 8];   // 2 x 16KB input stages
    __shared__ float s_out[2][JT * 9];       // 2 x 2.25KB transpose buffers (stride 9)

    unsigned g  = blockIdx.x;
    unsigned tg = g & 31u;                   // 32 tile-groups of NT=4 tiles
    unsigned bg = (g >> 5) & 7u;             // 8 groups of 8 b-rows
    unsigned c  = g >> 8;                    // 0..9

    unsigned t = threadIdx.x;
    unsigned w = t >> 5;                     // warp -> row
    unsigned l = t & 31u;                    // lane
    unsigned b = bg * RT + w;

    // warp w's row, this block's 4-tile span (4 * 2KB per row)
    const char* src = (const char*)(x + (size_t)b * (C * D) + (size_t)c * D
                                      + (size_t)tg * (NT * JT * 8u))
                    + l * 64u;               // thread's 64B slice of the 2KB tile-row

    // smem dst (u32 shared address) for this thread's 64B slice, per stage
    unsigned dst0 = (unsigned)__cvta_generic_to_shared(&s_in[0][w * 512u + l * 16u]);
    unsigned dst1 = (unsigned)__cvta_generic_to_shared(&s_in[1][w * 512u + l * 16u]);

    // prefetch tile 0 into stage 0
#pragma unroll
    for (int k = 0; k < 4; k++) CP_ASYNC16(dst0 + k * 16u, src + k * 16);
    CP_COMMIT();

#pragma unroll
    for (int tt = 0; tt < (int)NT; tt++) {
        // prefetch tile tt+1 into the other stage
        if (tt + 1 < (int)NT) {
            unsigned d = ((tt + 1) & 1) ? dst1 : dst0;
            const char* s = src + (size_t)(tt + 1) * 2048u;
#pragma unroll
            for (int k = 0; k < 4; k++) CP_ASYNC16(d + k * 16u, s + k * 16);
            CP_COMMIT();
            CP_WAIT(1);                      // tile tt complete, tt+1 in flight
        } else {
            CP_WAIT(0);
        }
        __syncwarp();                        // warp w only consumes its own row

        const float4* sr = reinterpret_cast<const float4*>(&s_in[tt & 1][w * 512u]);
        float* so = s_out[tt & 1];
#pragma unroll
        for (int it = 0; it < 2; it++) {
            float4 v0 = sr[(it * 32u + l) * 2u];
            float4 v1 = sr[(it * 32u + l) * 2u + 1u];
            so[(it * 32u + l) * 9u + w] = window_mode(v0, v1);
        }
        __syncthreads();                     // transpose handoff (only CTA barrier per tile)

        // store: thread -> (j = t>>3 (+32r), b_off = t&7); 32B-aligned full sectors
        float* ob = out + (size_t)c * (NJ * B)
                        + (size_t)(tg * NT + tt) * (JT * B) + (size_t)bg * RT;
        unsigned bo = t & 7u;
        unsigned j0 = t >> 3;                // 0..31
#pragma unroll
        for (int r = 0; r < 2; r++) {
            unsigned j = j0 + 32u * r;
            __stcs(&ob[(size_t)j * B + bo], so[j * 9u + bo]);
        }
        // s_out WAR across tiles is protected by the barrier of the next iteration
        // (buffer parity alternates; same-parity reuse is 2 barriers away).
    }
}

extern "C" void kernel_launch(void* const* d_in, const int* in_sizes, int n_in,
                              void* d_out, int out_size)
{
    const float* x = (const float*)d_in[0];
    float* out = (float*)d_out;
    // blocks = 32 tile-groups * 8 b-groups * 10 c = 2560, each does 4 tiles
    mode_pool_kernel<<<2560, 256>>>(x, out);
}

// round 7
// speedup vs baseline: 1.3393x; 1.3393x over previous
#include <cuda_runtime.h>
#include <cstdint>

// AdjustableModePooling:
//   x: (64, 65536, 10) f32 of integer labels 0..9, flat-viewed as (B=64, C=10, D=65536)
//   window K1=8 along D, mode per window (ties -> smallest value)
//   out flat index = c*(8192*64) + j*64 + b
//
// R7: persistent CTAs (grid=1024, one wave), each sweeps c=0..9 at fixed (jt,bg).
// Register double-buffer: tile i+1's LDGs issued before computing tile i ->
// loads in flight continuously, no wave transitions. One __syncthreads per tile
// (s_out double-buffered). Compute = R5's nibble-histogram mode.

static constexpr unsigned B  = 64;
static constexpr unsigned C  = 10;
static constexpr unsigned D  = 65536;
static constexpr unsigned NJ = 8192;     // (D-8)/8+1
static constexpr unsigned JT = 64;       // windows per tile (per row)
static constexpr unsigned RT = 8;        // rows per block = warps per block

__device__ __forceinline__ unsigned kmax(unsigned a, unsigned b) { return a > b ? a : b; }

__device__ __forceinline__ unsigned long long hist4(float a, float b_, float c_, float d_)
{
    // fma(f,4,2^23): bits = 0x4B000000 | 4v (exact for v in 0..9); bits&63 == 4v
    unsigned long long h = 0ull;
    h += 1ull << (__float_as_uint(__fmaf_rn(a,  4.0f, 8388608.0f)) & 63u);
    h += 1ull << (__float_as_uint(__fmaf_rn(b_, 4.0f, 8388608.0f)) & 63u);
    h += 1ull << (__float_as_uint(__fmaf_rn(c_, 4.0f, 8388608.0f)) & 63u);
    h += 1ull << (__float_as_uint(__fmaf_rn(d_, 4.0f, 8388608.0f)) & 63u);
    return h;
}

__device__ __forceinline__ float window_mode(float4 v0, float4 v1)
{
    unsigned long long acc = hist4(v0.x, v0.y, v0.z, v0.w)
                           + hist4(v1.x, v1.y, v1.z, v1.w);
    unsigned lo = (unsigned)acc;          // counts of v=0..7 in nibbles
    unsigned hi = (unsigned)(acc >> 32);  // counts of v=8,9

    // key_v = (count_v << 4) | (15 - v); max key wins; tie -> smallest v.
    unsigned k0 = ((lo << 4)  & 0xF0u) | 15u;
    unsigned k1 = ( lo        & 0xF0u) | 14u;
    unsigned k2 = ((lo >> 4)  & 0xF0u) | 13u;
    unsigned k3 = ((lo >> 8)  & 0xF0u) | 12u;
    unsigned k4 = ((lo >> 12) & 0xF0u) | 11u;
    unsigned k5 = ((lo >> 16) & 0xF0u) | 10u;
    unsigned k6 = ((lo >> 20) & 0xF0u) |  9u;
    unsigned k7 = ((lo >> 24) & 0xF0u) |  8u;
    unsigned k8 = ((hi << 4)  & 0xF0u) |  7u;
    unsigned k9 = ( hi        & 0xF0u) |  6u;

    unsigned m = kmax(kmax(kmax(k0, k1), kmax(k2, k3)),
                      kmax(kmax(k4, k5), kmax(k6, k7)));
    m = kmax(m, kmax(k8, k9));

    unsigned r = (~m) & 15u;             // mode = 15 - (m & 15)
    return __uint_as_float(0x4B000000u | r) - 8388608.0f;
}

__global__ __launch_bounds__(256, 5)
void mode_pool_kernel(const float* __restrict__ x, float* __restrict__ out)
{
    __shared__ float s_out[2][JT * 9];       // double-buffered transpose, stride 9

    unsigned bid = blockIdx.x;
    unsigned jt = bid & 127u;                // 128 j-tiles of 64 windows
    unsigned bg = bid >> 7;                  // 8 groups of 8 b-rows  (grid = 1024)

    unsigned t = threadIdx.x;
    unsigned w = t >> 5;                     // warp -> row
    unsigned l = t & 31u;                    // lane -> window
    unsigned b = bg * RT + w;

    // c advances with the loop: tile pointer strides by D floats per iteration
    const float4* rp = reinterpret_cast<const float4*>(
        x + (size_t)b * (C * D) + (size_t)jt * (JT * 8u));
    float* ob0 = out + (size_t)(jt * JT) * B + (size_t)bg * RT;

    unsigned bo = t & 7u;
    unsigned j0 = t >> 3;                    // 0..31

    float4 A0, A1, A2, A3, B0, B1, B2, B3;

    // preamble: load tile c=0 into A
    A0 = __ldcs(&rp[2 * l]);       A1 = __ldcs(&rp[2 * l + 1]);
    A2 = __ldcs(&rp[64 + 2 * l]);  A3 = __ldcs(&rp[64 + 2 * l + 1]);

#pragma unroll
    for (int c = 0; c < (int)C; c += 2) {
        // prefetch tile c+1 into B (c+1 <= 9 always)
        {
            const float4* pn = rp + (size_t)(c + 1) * (D / 4);
            B0 = __ldcs(&pn[2 * l]);       B1 = __ldcs(&pn[2 * l + 1]);
            B2 = __ldcs(&pn[64 + 2 * l]);  B3 = __ldcs(&pn[64 + 2 * l + 1]);
        }
        // compute + store tile c from A
        {
            float* so = s_out[0];
            so[l * 9u + w]         = window_mode(A0, A1);
            so[(32u + l) * 9u + w] = window_mode(A2, A3);
            __syncthreads();
            float* ob = ob0 + (size_t)c * (NJ * B);
#pragma unroll
            for (int r = 0; r < 2; r++) {
                unsigned j = j0 + 32u * r;
                __stcs(&ob[(size_t)j * B + bo], so[j * 9u + bo]);
            }
        }
        // prefetch tile c+2 into A (guarded)
        if (c + 2 < (int)C) {
            const float4* pn = rp + (size_t)(c + 2) * (D / 4);
            A0 = __ldcs(&pn[2 * l]);       A1 = __ldcs(&pn[2 * l + 1]);
            A2 = __ldcs(&pn[64 + 2 * l]);  A3 = __ldcs(&pn[64 + 2 * l + 1]);
        }
        // compute + store tile c+1 from B
        {
            float* so = s_out[1];
            so[l * 9u + w]         = window_mode(B0, B1);
            so[(32u + l) * 9u + w] = window_mode(B2, B3);
            __syncthreads();
            float* ob = ob0 + (size_t)(c + 1) * (NJ * B);
#pragma unroll
            for (int r = 0; r < 2; r++) {
                unsigned j = j0 + 32u * r;
                __stcs(&ob[(size_t)j * B + bo], so[j * 9u + bo]);
            }
        }
        // buffer parity alternates; same-parity reuse is two __syncthreads away -> safe
    }
}

extern "C" void kernel_launch(void* const* d_in, const int* in_sizes, int n_in,
                              void* d_out, int out_size)
{
    const float* x = (const float*)d_in[0];
    float* out = (float*)d_out;
    // persistent-ish single wave: 128 j-tiles * 8 b-groups = 1024 CTAs, c looped inside
    mode_pool_kernel<<<1024, 256>>>(x, out);
}

// round 8
// speedup vs baseline: 1.4308x; 1.0683x over previous
#include <cuda_runtime.h>
#include <cstdint>

// AdjustableModePooling:
//   x: (64, 65536, 10) f32 of integer labels 0..9, flat-viewed as (B=64, C=10, D=65536)
//   window K1=8 along D, mode per window (ties -> smallest value)
//   out flat index = c*(8192*64) + j*64 + b
//
// R8 = R5 base (best: 33.2us) + micro-combo:
//  - plain LDG (no .cs) for the paired half-sector loads
//  - argmax: all 10 keys in 3 byte-packed words, folded with __vmaxu4
//  - STG.64 stores (float2) from the smem transpose

static constexpr unsigned B  = 64;
static constexpr unsigned C  = 10;
static constexpr unsigned D  = 65536;
static constexpr unsigned NJ = 8192;     // (D-8)/8+1
static constexpr unsigned JT = 64;       // windows per block tile (per row)
static constexpr unsigned RT = 8;        // rows (b values) per block = warps per block

__device__ __forceinline__ unsigned long long hist4(float a, float b_, float c_, float d_)
{
    // fma(f,4,2^23): bits = 0x4B000000 | 4v (exact for v in 0..9); bits&63 == 4v
    unsigned long long h = 0ull;
    h += 1ull << (__float_as_uint(__fmaf_rn(a,  4.0f, 8388608.0f)) & 63u);
    h += 1ull << (__float_as_uint(__fmaf_rn(b_, 4.0f, 8388608.0f)) & 63u);
    h += 1ull << (__float_as_uint(__fmaf_rn(c_, 4.0f, 8388608.0f)) & 63u);
    h += 1ull << (__float_as_uint(__fmaf_rn(d_, 4.0f, 8388608.0f)) & 63u);
    return h;
}

__device__ __forceinline__ float window_mode(float4 v0, float4 v1)
{
    unsigned long long acc = hist4(v0.x, v0.y, v0.z, v0.w)
                           + hist4(v1.x, v1.y, v1.z, v1.w);
    unsigned lo = (unsigned)acc;          // counts of v=0..7 in nibbles 0..7
    unsigned hi = (unsigned)(acc >> 32);  // counts of v=8 (nib0), v=9 (nib1)

    // key_v = (count_v << 4) | (15 - v); max key wins; tie -> smallest v.
    // Byte-packed: E holds v=0,2,4,6 ; O holds v=1,3,5,7 ; H holds v=8,9.
    unsigned E = ((lo << 4) & 0xF0F0F0F0u) | 0x090B0D0Fu;
    unsigned O = ( lo       & 0xF0F0F0F0u) | 0x080A0C0Eu;
    unsigned H = (((hi << 4) & 0xF0u) | ((hi << 8) & 0xF000u)) | 0x0607u;

    unsigned M = __vmaxu4(__vmaxu4(E, O), H);
    M = __vmaxu4(M, M >> 16);
    M = __vmaxu4(M, M >> 8);              // byte0 = max key

    // mode = 15 - (M & 15) = (~M) & 15 ; int->float via exponent magic (no I2F)
    unsigned r = (~M) & 15u;
    return __uint_as_float(0x4B000000u | r) - 8388608.0f;
}

__global__ __launch_bounds__(256, 7)
void mode_pool_kernel(const float* __restrict__ x, float* __restrict__ out)
{
    __shared__ float s_out[JT * 9];          // [j_local][row], stride 9 -> no bank conflicts

    unsigned g  = blockIdx.x;
    unsigned jt = g & 127u;                  // 128 j-tiles of 64 windows
    unsigned bg = (g >> 7) & 7u;             // 8 groups of 8 b-rows
    unsigned c  = g >> 10;                   // 0..9

    unsigned t = threadIdx.x;
    unsigned w = t >> 5;                     // warp -> row within group
    unsigned l = t & 31u;                    // lane -> window within 32-window chunk
    unsigned b = bg * RT + w;

    const float4* rp = reinterpret_cast<const float4*>(
        x + (size_t)b * (C * D) + (size_t)c * D + (size_t)jt * (JT * 8u));

    // 2 chunks of 32 windows; lane l's window in chunk it = float4s (it*64 + 2l, +1).
    float4 v[4];
#pragma unroll
    for (int it = 0; it < 2; it++) {
        v[2 * it]     = rp[it * 64 + 2 * l];
        v[2 * it + 1] = rp[it * 64 + 2 * l + 1];
    }

#pragma unroll
    for (int it = 0; it < 2; it++) {
        float m = window_mode(v[2 * it], v[2 * it + 1]);
        s_out[(it * 32u + l) * 9u + w] = m;  // banks (9*l + w) % 32 -> conflict-free
    }
    __syncthreads();

    // Store phase: thread t -> (j = t>>2 (+64r), b_pair = t&3); STG.64, warp covers
    // 8 j-rows x 8 b = full 32B sectors (bg*8 floats is 32B aligned).
    float* ob = out + (size_t)c * (NJ * B) + (size_t)(jt * JT) * B + (size_t)bg * RT;
    unsigned bp = (t & 3u) * 2u;             // 0,2,4,6
    unsigned j0 = t >> 2;                    // 0..63
#pragma unroll
    for (int r = 0; r < 1; r++) { }          // (JT=64: one pass below)
    {
        unsigned j = j0;
        float2 val = make_float2(s_out[j * 9u + bp], s_out[j * 9u + bp + 1u]);
        __stcs(reinterpret_cast<float2*>(&ob[(size_t)j * B + bp]), val);
    }
}

extern "C" void kernel_launch(void* const* d_in, const int* in_sizes, int n_in,
                              void* d_out, int out_size)
{
    const float* x = (const float*)d_in[0];
    float* out = (float*)d_out;
    // blocks = 128 j-tiles * 8 b-groups * 10 c = 10240
    mode_pool_kernel<<<10240, 256>>>(x, out);
}